// round 16
// baseline (speedup 1.0000x reference)
#include <cuda_runtime.h>
#include <cuda_bf16.h>
#include <cuda_fp16.h>
#include <cstdint>

#define NN   4096
#define DIM  256
#define NH   4
#define HD   64
#define NE   131072
#define EDIM 64
#define LN_EPS 1e-5f
#define BCAP 24                        // per-warp sub-bucket capacity (lambda=4)
#define NBKT (64 * 64 * 8)             // nb x mchunk x warp-subtile

#define QSC  0.18033688011112042f     // 0.125 * log2(e)
#define C10  14.426950408889634f      // 10 * log2(e)
#define CB  -23.083120654223414f      // -16 * log2(e)

// ---------------- device scratch ----------------
__device__ __half g_Qh[NH * NN * HD];                             // [h][n][d] fp16 (scaled)
__device__ __half g_Kh[NH * NN * HD];                             // [h][m][d] fp16
__device__ __half g_Vh[NH * HD * NN];                             // [h][d][m] fp16
__device__ __half g_Xf[NN * DIM];                                 // X fp16
__device__ __half g_Wtf[4 * DIM * DIM];                           // W^T fp16 (q,k,v,o)
__device__ __half g_Of[NN * DIM];                                 // attn out fp16
__device__ float g_EA[(size_t)NE * NH];       // edge bias * 0.1
__device__ int   g_bcnt[NBKT];
__device__ int   g_blist[NBKT * BCAP];

// ---------------- helpers ----------------
__device__ __forceinline__ uint32_t smem_to_u32(const void* p) {
    uint32_t a;
    asm("{ .reg .u64 t; cvta.to.shared.u64 t, %1; cvt.u32.u64 %0, t; }" : "=r"(a) : "l"(p));
    return a;
}
#define SW128(b) ((b) ^ (((b) >> 3) & 0x70))
#define CP_ASYNC16(dst, src) \
    asm volatile("cp.async.cg.shared.global [%0], [%1], 16;" :: "r"(dst), "l"(src))
#define CP_COMMIT() asm volatile("cp.async.commit_group;" ::: "memory")
#define CP_WAIT0()  asm volatile("cp.async.wait_group 0;" ::: "memory")

__device__ __forceinline__ void ldsm4(uint32_t r[4], uint32_t addr) {
    asm volatile("ldmatrix.sync.aligned.m8n8.x4.shared.b16 {%0,%1,%2,%3}, [%4];"
        : "=r"(r[0]), "=r"(r[1]), "=r"(r[2]), "=r"(r[3]) : "r"(addr));
}
__device__ __forceinline__ void mma_f16(float c[4], const uint32_t a[4],
                                        uint32_t b0, uint32_t b1) {
    asm volatile("mma.sync.aligned.m16n8k16.row.col.f32.f16.f16.f32 "
        "{%0,%1,%2,%3}, {%4,%5,%6,%7}, {%8,%9}, {%0,%1,%2,%3};"
        : "+f"(c[0]), "+f"(c[1]), "+f"(c[2]), "+f"(c[3])
        : "r"(a[0]), "r"(a[1]), "r"(a[2]), "r"(a[3]), "r"(b0), "r"(b1));
}
__device__ __forceinline__ float ex2(float x) {
    float r;
    asm("ex2.approx.f32 %0, %1;" : "=f"(r) : "f"(x));
    return r;
}
__device__ __forceinline__ uint32_t cvtf16(float lo, float hi) { // packed f16 {lo, hi}
    uint32_t r;
    asm("cvt.rn.f16x2.f32 %0, %1, %2;" : "=r"(r) : "f"(hi), "f"(lo));
    return r;
}

// =====================================================================
// K0: merged split kernel. z<4: transpose W plane z -> fp16.
// z==4: X -> fp16 (also zeros g_bcnt: 64 blocks x 512 ints).
// =====================================================================
__global__ void k_split(const float* __restrict__ X,
                        const float* __restrict__ Wq, const float* __restrict__ Wk,
                        const float* __restrict__ Wv, const float* __restrict__ Wo) {
    const int z = blockIdx.z;
    const int t = threadIdx.x;
    if (z == 4) {
        int flat = blockIdx.y * 8 + blockIdx.x;
        g_bcnt[flat * 512 + t] = 0;
        g_bcnt[flat * 512 + 256 + t] = 0;
#pragma unroll
        for (int k = 0; k < 16; k++) {
            int i = flat * 256 + t + k * 16384;
            float4 v = ((const float4*)X)[i];
            uint2 hp;
            hp.x = cvtf16(v.x, v.y);
            hp.y = cvtf16(v.z, v.w);
            ((uint2*)g_Xf)[i] = hp;
        }
        return;
    }
    __shared__ float tile[32][33];
    const float* W = (z == 0) ? Wq : (z == 1) ? Wk : (z == 2) ? Wv : Wo;
    const int bx = blockIdx.x * 32, by = blockIdx.y * 32;
    const int tx = t & 31, ty = t >> 5;
#pragma unroll
    for (int i = 0; i < 4; i++) {
        int k = by + ty + 8 * i;
        tile[ty + 8 * i][tx] = W[k * DIM + bx + tx];
    }
    __syncthreads();
#pragma unroll
    for (int i = 0; i < 4; i++) {
        int n = bx + ty + 8 * i;
        float v = tile[tx][ty + 8 * i];
        g_Wtf[z * DIM * DIM + n * DIM + by + tx] = __float2half_rn(v);
    }
}

// =====================================================================
// K2: per-edge bias GEMM -> g_EA (x 0.1); per-warp-subtile bucket scatter.
// key = (src>>6)*64*8 + (tgt>>6)*8 + ((src>>4)&3)*2 + ((tgt>>5)&1)
// =====================================================================
__global__ void k_ea(const float* __restrict__ EF, const int* __restrict__ EI,
                     const float* __restrict__ We, const float* __restrict__ be) {
    __shared__ float ef[64][65];
    __shared__ float w[EDIM][NH];
    __shared__ float bsh[NH];
    const int t  = threadIdx.x;
    const int e0 = blockIdx.x * 64;
#pragma unroll
    for (int i = 0; i < 16; i++) {
        int idx = t + 256 * i;
        ef[idx >> 6][idx & 63] = EF[(size_t)e0 * EDIM + idx];
    }
    if (t < EDIM * NH) w[t >> 2][t & 3] = We[t];
    if (t < NH) bsh[t] = be[t];
    __syncthreads();

    const int el = t >> 2, h = t & 3;
    const int e = e0 + el;
    float s = bsh[h];
#pragma unroll
    for (int k = 0; k < EDIM; k++) s += ef[el][k] * w[k][h];
    g_EA[(size_t)e * NH + h] = s * 0.1f;
    if (h == 0) {
        int src = EI[2 * e], tgt = EI[2 * e + 1];
        int key = (((src >> 6) * 64 + ((tgt >> 6) & 63)) << 3)
                  + ((src >> 4) & 3) * 2 + ((tgt >> 5) & 1);
        int pos = atomicAdd(&g_bcnt[key], 1);
        if (pos < BCAP) g_blist[key * BCAP + pos] = e;
    }
}

// =====================================================================
// K1: QKV projection on tensor cores, single fp16 products.
// =====================================================================
#define PJ_BUF(b) ((b) * 24576u)
#define PJ_SMEM   49152

__global__ void __launch_bounds__(256, 2) k_proj_tc(
        const float* __restrict__ bq, const float* __restrict__ bk,
        const float* __restrict__ bv) {
    extern __shared__ char smem[];
    const uint32_t sb = smem_to_u32(smem);
    const int t = threadIdx.x, lane = t & 31, w = t >> 5;
    const int wr = w & 3, wc = w >> 2;
    const int h = blockIdx.x, c0 = h * 64;
    const int n0 = blockIdx.y * 128;
    const int z = blockIdx.z;
    const float* bias = (z == 0) ? bq : (z == 1) ? bk : bv;
    const __half* Wtf = g_Wtf + z * DIM * DIM;

    const int g = lane >> 2, tg = lane & 3;
    const uint32_t cOff = (lane >> 4) * 16;

#pragma unroll
    for (int i = 0; i < 4; i++) {
        int e = t + 256 * i;
        int row = e >> 3, c8 = e & 7;
        uint32_t sw = SW128((uint32_t)(row * 128 + c8 * 16));
        CP_ASYNC16(sb + PJ_BUF(0) + sw, g_Xf + (size_t)(n0 + row) * DIM + c8 * 8);
    }
#pragma unroll
    for (int i = 0; i < 2; i++) {
        int e = t + 256 * i;
        int row = e >> 3, c8 = e & 7;
        uint32_t sw = SW128((uint32_t)(row * 128 + c8 * 16));
        CP_ASYNC16(sb + PJ_BUF(0) + 16384 + sw, Wtf + (size_t)(c0 + row) * DIM + c8 * 8);
    }
    CP_COMMIT();
    CP_WAIT0();
    __syncthreads();

    float acc[2][4][4];
#pragma unroll
    for (int f = 0; f < 2; f++)
#pragma unroll
        for (int fm = 0; fm < 4; fm++)
#pragma unroll
            for (int k = 0; k < 4; k++) acc[f][fm][k] = 0.f;

    for (int ch = 0; ch < 4; ch++) {
        const int b = ch & 1;
        if (ch < 3) {
            const int kc = (ch + 1) * 64;
#pragma unroll
            for (int i = 0; i < 4; i++) {
                int e = t + 256 * i;
                int row = e >> 3, c8 = e & 7;
                uint32_t sw = SW128((uint32_t)(row * 128 + c8 * 16));
                CP_ASYNC16(sb + PJ_BUF(b ^ 1) + sw,
                           g_Xf + (size_t)(n0 + row) * DIM + kc + c8 * 8);
            }
#pragma unroll
            for (int i = 0; i < 2; i++) {
                int e = t + 256 * i;
                int row = e >> 3, c8 = e & 7;
                uint32_t sw = SW128((uint32_t)(row * 128 + c8 * 16));
                CP_ASYNC16(sb + PJ_BUF(b ^ 1) + 16384 + sw,
                           Wtf + (size_t)(c0 + row) * DIM + kc + c8 * 8);
            }
            CP_COMMIT();
        }
        const uint32_t sA = sb + PJ_BUF(b), sB = sA + 16384;
#pragma unroll
        for (int ks = 0; ks < 4; ks++) {
            uint32_t aH[2][4], bH[2][4];
#pragma unroll
            for (int f = 0; f < 2; f++) {
                uint32_t byte = (wr * 32 + f * 16 + (lane & 15)) * 128 + ks * 32 + cOff;
                ldsm4(aH[f], sA + SW128(byte));
            }
#pragma unroll
            for (int fg = 0; fg < 2; fg++) {
                uint32_t byte = (wc * 32 + fg * 16 + (lane & 15)) * 128 + ks * 32 + cOff;
                ldsm4(bH[fg], sB + SW128(byte));
            }
#pragma unroll
            for (int f = 0; f < 2; f++)
#pragma unroll
                for (int fg = 0; fg < 2; fg++) {
                    mma_f16(acc[f][2*fg],   aH[f], bH[fg][0], bH[fg][2]);
                    mma_f16(acc[f][2*fg+1], aH[f], bH[fg][1], bH[fg][3]);
                }
        }
        if (ch < 3) CP_WAIT0();
        __syncthreads();
    }

    // epilogue
#pragma unroll
    for (int f = 0; f < 2; f++) {
        int row0 = n0 + wr * 32 + f * 16 + g;
#pragma unroll
        for (int fm = 0; fm < 4; fm++) {
            int cl = wc * 32 + fm * 8 + tg * 2;
            float b0 = bias[c0 + cl], b1 = bias[c0 + cl + 1];
            float v0 = acc[f][fm][0] + b0, v1 = acc[f][fm][1] + b1;
            float v2 = acc[f][fm][2] + b0, v3 = acc[f][fm][3] + b1;
            if (z == 0) { v0 *= QSC; v1 *= QSC; v2 *= QSC; v3 *= QSC; }
            if (z < 2) {
                __half* dst = (z == 0) ? g_Qh : g_Kh;
                size_t i0 = ((size_t)h * NN + row0) * HD + cl;
                size_t i8 = ((size_t)h * NN + row0 + 8) * HD + cl;
                *(uint32_t*)&dst[i0] = cvtf16(v0, v1);
                *(uint32_t*)&dst[i8] = cvtf16(v2, v3);
            } else {
                float vv[4] = {v0, v1, v2, v3};
#pragma unroll
                for (int q = 0; q < 4; q++) {
                    int d = cl + (q & 1);
                    int m = row0 + (q >> 1) * 8;
                    g_Vh[((size_t)h * HD + d) * NN + m] = __float2half_rn(vv[q]);
                }
            }
        }
    }
}

// =====================================================================
// K3: FUSED attention v9. QK/PV fp16 single. ONE barrier per m-chunk:
// edge scatter is warp-local (per-warp sub-buckets) -> __syncwarp only.
// smem: ADJ(b) @b*17408 | KV(b) @34816+b*16384 | sums @67584 ; 68096 B
// =====================================================================
#define FB_ADJ(b) ((b) * 17408u)
#define FB_KV(b)  (34816u + (b) * 16384u)
#define FB_SUM    67584u
#define FS_SMEM   68096

__global__ void __launch_bounds__(256, 2) k_fused(const float* __restrict__ adj,
                                                  const int* __restrict__ EI) {
    extern __shared__ char smem[];
    const uint32_t sb = smem_to_u32(smem);
    const int t = threadIdx.x, lane = t & 31, w = t >> 5;
    const int wr = w & 3, wc = w >> 2;
    const int h = blockIdx.x, nb = blockIdx.y, n0 = nb * 64;
    const int subkey = wr * 2 + wc;     // matches (row>>4)*2 + (col>>5)

    const int g  = lane >> 2, tg = lane & 3;
    const int rl = wr * 16 + g;
    const uint32_t aRow = wr * 16 + (lane & 15);
    const uint32_t cOff = (lane >> 4) * 16;

    const __half* Khb = g_Kh + (size_t)h * NN * HD;
    const __half* Vhb = g_Vh + (size_t)h * HD * NN;

    // ---------- prologue ----------
    const int kvc = t & 7;
#pragma unroll
    for (int i = 0; i < 2; i++) {
        int r = (t >> 3) + 32 * i;
        uint32_t sw = SW128((uint32_t)(r * 128 + kvc * 16));
        CP_ASYNC16(sb + FB_KV(0) + sw,         Khb + (size_t)r * HD + kvc * 8);
        CP_ASYNC16(sb + FB_KV(0) + 8192 + sw,  Vhb + (size_t)r * NN + kvc * 8);
    }
    CP_COMMIT();
    {
        const uint4* qh = (const uint4*)(g_Qh + ((size_t)h * NN + n0) * HD);
#pragma unroll
        for (int i = 0; i < 2; i++) {
            int e = t + 256 * i;
            uint32_t sw = SW128((uint32_t)e * 16);
            *(uint4*)(smem + FB_ADJ(0) + sw) = qh[e];
        }
    }
    __syncthreads();

    uint32_t aQH[4][4];
#pragma unroll
    for (int ks = 0; ks < 4; ks++) {
        uint32_t byte = aRow * 128 + ks * 32 + cOff;
        ldsm4(aQH[ks], sb + FB_ADJ(0) + SW128(byte));
    }
    __syncthreads();

#pragma unroll
    for (int i = 0; i < 4; i++) {
        int idx = t + 256 * i;
        int row = idx >> 4, c4 = idx & 15;
        CP_ASYNC16(sb + FB_ADJ(0) + (uint32_t)(row * 272 + c4 * 16),
                   adj + (size_t)(n0 + row) * NN + c4 * 4);
    }
    CP_COMMIT();
    CP_WAIT0();
    __syncthreads();

    float oacc[8][4];
#pragma unroll
    for (int fd = 0; fd < 8; fd++)
#pragma unroll
        for (int k = 0; k < 4; k++) oacc[fd][k] = 0.f;
    float rs0a = 0.f, rs0b = 0.f, rs8a = 0.f, rs8b = 0.f;

    for (int j = 0; j < 64; j++) {
        const int b = j & 1;
        const uint32_t sKH = sb + FB_KV(b);
        const uint32_t sVH = sKH + 8192;
        float* At = (float*)(smem + FB_ADJ(b));

        // ---- warp-local edge scatter into own At sub-tile ----
        {
            int key = ((nb * 64 + j) << 3) + subkey;
            int cnt = g_bcnt[key];
            const int* bl = g_blist + key * BCAP;
            for (int i = lane; i < cnt; i += 32) {
                int e = bl[i];
                atomicAdd(&At[(EI[2 * e] & 63) * 68 + (EI[2 * e + 1] & 63)],
                          g_EA[(size_t)e * NH + h]);
            }
        }

        // ---- QK mma ----
        float qk[4][4];
#pragma unroll
        for (int fi = 0; fi < 4; fi++)
#pragma unroll
            for (int k = 0; k < 4; k++) qk[fi][k] = CB;
#pragma unroll
        for (int ks = 0; ks < 4; ks++) {
            uint32_t bH[2][4];
#pragma unroll
            for (int fg = 0; fg < 2; fg++) {
                uint32_t bb = (wc * 32 + fg * 16 + (lane & 15)) * 128 + ks * 32 + cOff;
                ldsm4(bH[fg], sKH + SW128(bb));
            }
#pragma unroll
            for (int fg = 0; fg < 2; fg++) {
                mma_f16(qk[2*fg],   aQH[ks], bH[fg][0], bH[fg][2]);
                mma_f16(qk[2*fg+1], aQH[ks], bH[fg][1], bH[fg][3]);
            }
        }

        // ---- cp.async next chunk ----
        if (j < 63) {
            const int m1 = (j + 1) * 64;
#pragma unroll
            for (int i = 0; i < 2; i++) {
                int r = (t >> 3) + 32 * i;
                uint32_t sw = SW128((uint32_t)(r * 128 + kvc * 16));
                CP_ASYNC16(sb + FB_KV(b ^ 1) + sw,        Khb + (size_t)(m1 + r) * HD + kvc * 8);
                CP_ASYNC16(sb + FB_KV(b ^ 1) + 8192 + sw, Vhb + (size_t)r * NN + m1 + kvc * 8);
            }
#pragma unroll
            for (int i = 0; i < 4; i++) {
                int idx = t + 256 * i;
                int row = idx >> 4, c4 = idx & 15;
                CP_ASYNC16(sb + FB_ADJ(b ^ 1) + (uint32_t)(row * 272 + c4 * 16),
                           adj + (size_t)(n0 + row) * NN + m1 + c4 * 4);
            }
            CP_COMMIT();
        }
        __syncwarp();   // scatter visible to own warp

        // ---- exp -> P regs; PV mma ----
        uint32_t pH0[4], pH8[4];
        const float* At0 = At + rl * 68 + wc * 32 + tg * 2;
        const float* At8 = At0 + 8 * 68;
#pragma unroll
        for (int fi = 0; fi < 4; fi++) {
            float2 a0 = *(const float2*)(At0 + fi * 8);
            float2 a8 = *(const float2*)(At8 + fi * 8);
            float p0 = ex2(fmaf(C10, a0.x, qk[fi][0]));
            float p1 = ex2(fmaf(C10, a0.y, qk[fi][1]));
            float p2 = ex2(fmaf(C10, a8.x, qk[fi][2]));
            float p3 = ex2(fmaf(C10, a8.y, qk[fi][3]));
            if (fi & 1) { rs0b += p0 + p1; rs8b += p2 + p3; }
            else        { rs0a += p0 + p1; rs8a += p2 + p3; }
            pH0[fi] = cvtf16(p0, p1);
            pH8[fi] = cvtf16(p2, p3);
        }
#pragma unroll
        for (int ks2 = 0; ks2 < 2; ks2++) {
            uint32_t aH[4] = {pH0[2*ks2], pH8[2*ks2], pH0[2*ks2+1], pH8[2*ks2+1]};
#pragma unroll
            for (int fg = 0; fg < 4; fg++) {
                uint32_t bb = (fg * 16 + (lane & 15)) * 128 + wc * 64 + ks2 * 32 + cOff;
                uint32_t bH[4];
                ldsm4(bH, sVH + SW128(bb));
                mma_f16(oacc[2*fg],   aH, bH[0], bH[2]);
                mma_f16(oacc[2*fg+1], aH, bH[1], bH[3]);
            }
        }
        CP_WAIT0();
        __syncthreads();   // single barrier per iter
    }

    // ---- epilogue: write O as single fp16 ----
    float rowsum0 = rs0a + rs0b, rowsum8 = rs8a + rs8b;
    rowsum0 += __shfl_xor_sync(0xffffffffu, rowsum0, 1);
    rowsum0 += __shfl_xor_sync(0xffffffffu, rowsum0, 2);
    rowsum8 += __shfl_xor_sync(0xffffffffu, rowsum8, 1);
    rowsum8 += __shfl_xor_sync(0xffffffffu, rowsum8, 2);
    float* sums = (float*)(smem + FB_SUM);
    if (tg == 0) {
        sums[wc * 64 + rl] = rowsum0;
        sums[wc * 64 + rl + 8] = rowsum8;
    }
    float* buf = (float*)(smem + FB_ADJ(0));
    __syncthreads();
    if (wc == 1) {
#pragma unroll
        for (int fd = 0; fd < 8; fd++) {
            int col = (fd >> 1) * 16 + (fd & 1) * 8 + tg * 2;
            buf[rl * 68 + col]           = oacc[fd][0];
            buf[rl * 68 + col + 1]       = oacc[fd][1];
            buf[(rl + 8) * 68 + col]     = oacc[fd][2];
            buf[(rl + 8) * 68 + col + 1] = oacc[fd][3];
        }
    }
    __syncthreads();
    if (wc == 0) {
        const float ri0 = 1.f / (sums[rl] + sums[64 + rl]);
        const float ri8 = 1.f / (sums[rl + 8] + sums[64 + rl + 8]);
#pragma unroll
        for (int fd = 0; fd < 8; fd++) {
            int col = (fd >> 1) * 16 + (fd & 1) * 8 + tg * 2;
            float v0 = (oacc[fd][0] + buf[rl * 68 + col]) * ri0;
            float v1 = (oacc[fd][1] + buf[rl * 68 + col + 1]) * ri0;
            float v2 = (oacc[fd][2] + buf[(rl + 8) * 68 + col]) * ri8;
            float v3 = (oacc[fd][3] + buf[(rl + 8) * 68 + col + 1]) * ri8;
            size_t i0 = (size_t)(n0 + rl) * DIM + h * HD + col;
            size_t i8 = (size_t)(n0 + rl + 8) * DIM + h * HD + col;
            *(uint32_t*)&g_Of[i0] = cvtf16(v0, v1);
            *(uint32_t*)&g_Of[i8] = cvtf16(v2, v3);
        }
    }
}

// =====================================================================
// K4: output projection (fp16 single) + residual + LayerNorm.
// =====================================================================
#define OP_BUF(b) ((b) * 36864u)
#define OP_SUM    73728u
#define OP_SMEM   74880

__global__ void __launch_bounds__(256, 2) k_oproj_ln(
        const float* __restrict__ bo, const float* __restrict__ X,
        const float* __restrict__ gamma, const float* __restrict__ beta,
        float* __restrict__ out) {
    extern __shared__ char smem[];
    const uint32_t sb = smem_to_u32(smem);
    const int t = threadIdx.x, lane = t & 31, w = t >> 5;
    const int r0 = blockIdx.x * 32;
    const int g = lane >> 2, tg = lane & 3;
    const uint32_t cOff = (lane >> 4) * 16;
    const __half* Wtf = g_Wtf + 3 * DIM * DIM;

    {
        int row = t >> 3, c8 = t & 7;
        uint32_t sw = SW128((uint32_t)(row * 128 + c8 * 16));
        CP_ASYNC16(sb + OP_BUF(0) + sw, g_Of + (size_t)(r0 + row) * DIM + c8 * 8);
#pragma unroll
        for (int i = 0; i < 8; i++) {
            int rb = (t >> 3) + 32 * i;
            uint32_t swb = SW128((uint32_t)(rb * 128 + c8 * 16));
            CP_ASYNC16(sb + OP_BUF(0) + 4096 + swb, Wtf + (size_t)rb * DIM + c8 * 8);
        }
    }
    CP_COMMIT();
    CP_WAIT0();
    __syncthreads();

    float acc[2][4][4];
#pragma unroll
    for (int f = 0; f < 2; f++)
#pragma unroll
        for (int fm = 0; fm < 4; fm++)
#pragma unroll
            for (int k = 0; k < 4; k++) acc[f][fm][k] = 0.f;

    for (int ch = 0; ch < 4; ch++) {
        const int b = ch & 1;
        if (ch < 3) {
            const int kc = (ch + 1) * 64;
            int row = t >> 3, c8 = t & 7;
            uint32_t sw = SW128((uint32_t)(row * 128 + c8 * 16));
            CP_ASYNC16(sb + OP_BUF(b ^ 1) + sw,
                       g_Of + (size_t)(r0 + row) * DIM + kc + c8 * 8);
#pragma unroll
            for (int i = 0; i < 8; i++) {
                int rb = (t >> 3) + 32 * i;
                uint32_t swb = SW128((uint32_t)(rb * 128 + c8 * 16));
                CP_ASYNC16(sb + OP_BUF(b ^ 1) + 4096 + swb,
                           Wtf + (size_t)rb * DIM + kc + c8 * 8);
            }
            CP_COMMIT();
        }
        const uint32_t sA = sb + OP_BUF(b), sB = sA + 4096;
#pragma unroll
        for (int ks = 0; ks < 4; ks++) {
            uint32_t aH[2][4], bH[2][4];
#pragma unroll
            for (int f = 0; f < 2; f++) {
                uint32_t byte = (f * 16 + (lane & 15)) * 128 + ks * 32 + cOff;
                ldsm4(aH[f], sA + SW128(byte));
            }
#pragma unroll
            for (int fg = 0; fg < 2; fg++) {
                uint32_t byte = (w * 32 + fg * 16 + (lane & 15)) * 128 + ks * 32 + cOff;
                ldsm4(bH[fg], sB + SW128(byte));
            }
#pragma unroll
            for (int f = 0; f < 2; f++)
#pragma unroll
                for (int fg = 0; fg < 2; fg++) {
                    mma_f16(acc[f][2*fg],   aH[f], bH[fg][0], bH[fg][2]);
                    mma_f16(acc[f][2*fg+1], aH[f], bH[fg][1], bH[fg][3]);
                }
        }
        if (ch < 3) CP_WAIT0();
        __syncthreads();
    }

    // bias + residual
#pragma unroll
    for (int f = 0; f < 2; f++) {
#pragma unroll
        for (int fm = 0; fm < 4; fm++) {
            int col = w * 32 + fm * 8 + tg * 2;
            float2 bb = *(const float2*)&bo[col];
            float2 x0 = *(const float2*)&X[(size_t)(r0 + f * 16 + g) * DIM + col];
            float2 x8 = *(const float2*)&X[(size_t)(r0 + f * 16 + g + 8) * DIM + col];
            acc[f][fm][0] += bb.x + x0.x;
            acc[f][fm][1] += bb.y + x0.y;
            acc[f][fm][2] += bb.x + x8.x;
            acc[f][fm][3] += bb.y + x8.y;
        }
    }

    // LayerNorm: cross-warp reduce via smem [32][9]
    float* sums = (float*)(smem + OP_SUM);
#pragma unroll
    for (int f = 0; f < 2; f++) {
        float s0 = 0.f, s8 = 0.f;
#pragma unroll
        for (int fm = 0; fm < 4; fm++) {
            s0 += acc[f][fm][0] + acc[f][fm][1];
            s8 += acc[f][fm][2] + acc[f][fm][3];
        }
        s0 += __shfl_xor_sync(0xffffffffu, s0, 1);
        s0 += __shfl_xor_sync(0xffffffffu, s0, 2);
        s8 += __shfl_xor_sync(0xffffffffu, s8, 1);
        s8 += __shfl_xor_sync(0xffffffffu, s8, 2);
        if (tg == 0) {
            sums[(f * 16 + g) * 9 + w] = s0;
            sums[(f * 16 + g + 8) * 9 + w] = s8;
        }
    }
    __syncthreads();
    float mu[2][2];
#pragma unroll
    for (int f = 0; f < 2; f++) {
        float m0 = 0.f, m8 = 0.f;
#pragma unroll
        for (int ww = 0; ww < 8; ww++) {
            m0 += sums[(f * 16 + g) * 9 + ww];
            m8 += sums[(f * 16 + g + 8) * 9 + ww];
        }
        mu[f][0] = m0 * (1.f / DIM);
        mu[f][1] = m8 * (1.f / DIM);
    }
    __syncthreads();
#pragma unroll
    for (int f = 0; f < 2; f++) {
        float q0 = 0.f, q8 = 0.f;
#pragma unroll
        for (int fm = 0; fm < 4; fm++) {
            acc[f][fm][0] -= mu[f][0]; acc[f][fm][1] -= mu[f][0];
            acc[f][fm][2] -= mu[f][1]; acc[f][fm][3] -= mu[f][1];
            q0 += acc[f][fm][0] * acc[f][fm][0] + acc[f][fm][1] * acc[f][fm][1];
            q8 += acc[f][fm][2] * acc[f][fm][2] + acc[f][fm][3] * acc[f][fm][3];
        }
        q0 += __shfl_xor_sync(0xffffffffu, q0, 1);
        q0 += __shfl_xor_sync(0xffffffffu, q0, 2);
        q8 += __shfl_xor_sync(0xffffffffu, q8, 1);
        q8 += __shfl_xor_sync(0xffffffffu, q8, 2);
        if (tg == 0) {
            sums[(f * 16 + g) * 9 + w] = q0;
            sums[(f * 16 + g + 8) * 9 + w] = q8;
        }
    }
    __syncthreads();
#pragma unroll
    for (int f = 0; f < 2; f++) {
        float v0 = 0.f, v8 = 0.f;
#pragma unroll
        for (int ww = 0; ww < 8; ww++) {
            v0 += sums[(f * 16 + g) * 9 + ww];
            v8 += sums[(f * 16 + g + 8) * 9 + ww];
        }
        float rs0 = rsqrtf(v0 * (1.f / DIM) + LN_EPS);
        float rs8 = rsqrtf(v8 * (1.f / DIM) + LN_EPS);
#pragma unroll
        for (int fm = 0; fm < 4; fm++) {
            int col = w * 32 + fm * 8 + tg * 2;
            float2 gm = *(const float2*)&gamma[col];
            float2 bt = *(const float2*)&beta[col];
            float2 o0 = { gm.x * acc[f][fm][0] * rs0 + bt.x,
                          gm.y * acc[f][fm][1] * rs0 + bt.y };
            float2 o8 = { gm.x * acc[f][fm][2] * rs8 + bt.x,
                          gm.y * acc[f][fm][3] * rs8 + bt.y };
            *(float2*)&out[(size_t)(r0 + f * 16 + g) * DIM + col] = o0;
            *(float2*)&out[(size_t)(r0 + f * 16 + g + 8) * DIM + col] = o8;
        }
    }
}

// =====================================================================
extern "C" void kernel_launch(void* const* d_in, const int* in_sizes, int n_in,
                              void* d_out, int out_size) {
    const float* X    = (const float*)d_in[0];
    const float* adj  = (const float*)d_in[1];
    const float* EF   = (const float*)d_in[2];
    const int*   EI   = (const int*)  d_in[3];
    const float* Wq   = (const float*)d_in[4];
    const float* bq   = (const float*)d_in[5];
    const float* Wk   = (const float*)d_in[6];
    const float* bk   = (const float*)d_in[7];
    const float* Wv   = (const float*)d_in[8];
    const float* bv   = (const float*)d_in[9];
    const float* We   = (const float*)d_in[10];
    const float* be   = (const float*)d_in[11];
    const float* Wo   = (const float*)d_in[12];
    const float* bo   = (const float*)d_in[13];
    const float* gam  = (const float*)d_in[14];
    const float* bet  = (const float*)d_in[15];
    float* out = (float*)d_out;

    cudaFuncSetAttribute(k_proj_tc,  cudaFuncAttributeMaxDynamicSharedMemorySize, PJ_SMEM);
    cudaFuncSetAttribute(k_fused,    cudaFuncAttributeMaxDynamicSharedMemorySize, FS_SMEM);
    cudaFuncSetAttribute(k_oproj_ln, cudaFuncAttributeMaxDynamicSharedMemorySize, OP_SMEM);

    k_split   <<<dim3(8, 8, 5), 256>>>(X, Wq, Wk, Wv, Wo);
    k_ea      <<<NE / 64, 256>>>(EF, EI, We, be);
    k_proj_tc <<<dim3(4, 32, 3), 256, PJ_SMEM>>>(bq, bk, bv);
    k_fused   <<<dim3(NH, 64), 256, FS_SMEM>>>(adj, EI);
    k_oproj_ln<<<NN / 32, 256, OP_SMEM>>>(bo, X, gam, bet, out);
}

// round 17
// speedup vs baseline: 1.1681x; 1.1681x over previous
#include <cuda_runtime.h>
#include <cuda_bf16.h>
#include <cuda_fp16.h>
#include <cstdint>

#define NN   4096
#define DIM  256
#define NH   4
#define HD   64
#define NE   131072
#define EDIM 64
#define LN_EPS 1e-5f
#define BCAP 128

#define QSC  0.18033688011112042f     // 0.125 * log2(e)
#define C10  14.426950408889634f      // 10 * log2(e)
#define CB  -23.083120654223414f      // -16 * log2(e)

// ---------------- device scratch ----------------
__device__ __half g_Qh[NH * NN * HD];                             // [h][n][d] fp16 (scaled)
__device__ __half g_Kh[NH * NN * HD];                             // [h][m][d] fp16
__device__ __half g_Vh[NH * HD * NN];                             // [h][d][m] fp16
__device__ __half g_Xf[NN * DIM];                                 // X fp16
__device__ __half g_Wtf[4 * DIM * DIM];                           // W^T fp16 (q,k,v,o)
__device__ __half g_Of[NN * DIM];                                 // attn out fp16
__device__ float g_EA[(size_t)NE * NH];       // edge bias * 0.1
__device__ int   g_bcnt[4096];
__device__ int   g_blist[4096 * BCAP];

// ---------------- helpers ----------------
__device__ __forceinline__ uint32_t smem_to_u32(const void* p) {
    uint32_t a;
    asm("{ .reg .u64 t; cvta.to.shared.u64 t, %1; cvt.u32.u64 %0, t; }" : "=r"(a) : "l"(p));
    return a;
}
#define SW128(b) ((b) ^ (((b) >> 3) & 0x70))
#define CP_ASYNC16(dst, src) \
    asm volatile("cp.async.cg.shared.global [%0], [%1], 16;" :: "r"(dst), "l"(src))
#define CP_COMMIT() asm volatile("cp.async.commit_group;" ::: "memory")
#define CP_WAIT0()  asm volatile("cp.async.wait_group 0;" ::: "memory")

__device__ __forceinline__ void ldsm4(uint32_t r[4], uint32_t addr) {
    asm volatile("ldmatrix.sync.aligned.m8n8.x4.shared.b16 {%0,%1,%2,%3}, [%4];"
        : "=r"(r[0]), "=r"(r[1]), "=r"(r[2]), "=r"(r[3]) : "r"(addr));
}
__device__ __forceinline__ void mma_f16(float c[4], const uint32_t a[4],
                                        uint32_t b0, uint32_t b1) {
    asm volatile("mma.sync.aligned.m16n8k16.row.col.f32.f16.f16.f32 "
        "{%0,%1,%2,%3}, {%4,%5,%6,%7}, {%8,%9}, {%0,%1,%2,%3};"
        : "+f"(c[0]), "+f"(c[1]), "+f"(c[2]), "+f"(c[3])
        : "r"(a[0]), "r"(a[1]), "r"(a[2]), "r"(a[3]), "r"(b0), "r"(b1));
}
__device__ __forceinline__ float ex2(float x) {
    float r;
    asm("ex2.approx.f32 %0, %1;" : "=f"(r) : "f"(x));
    return r;
}
__device__ __forceinline__ uint32_t cvtf16(float lo, float hi) { // packed f16 {lo, hi}
    uint32_t r;
    asm("cvt.rn.f16x2.f32 %0, %1, %2;" : "=r"(r) : "f"(hi), "f"(lo));
    return r;
}

// =====================================================================
// K0: merged split kernel. z<4: transpose W plane z -> fp16.
// z==4: X -> fp16 (also zeros g_bcnt).
// =====================================================================
__global__ void k_split(const float* __restrict__ X,
                        const float* __restrict__ Wq, const float* __restrict__ Wk,
                        const float* __restrict__ Wv, const float* __restrict__ Wo) {
    const int z = blockIdx.z;
    const int t = threadIdx.x;
    if (z == 4) {
        int flat = blockIdx.y * 8 + blockIdx.x;
        if (flat < 16) g_bcnt[flat * 256 + t] = 0;
#pragma unroll
        for (int k = 0; k < 16; k++) {
            int i = flat * 256 + t + k * 16384;
            float4 v = ((const float4*)X)[i];
            uint2 hp;
            hp.x = cvtf16(v.x, v.y);
            hp.y = cvtf16(v.z, v.w);
            ((uint2*)g_Xf)[i] = hp;
        }
        return;
    }
    __shared__ float tile[32][33];
    const float* W = (z == 0) ? Wq : (z == 1) ? Wk : (z == 2) ? Wv : Wo;
    const int bx = blockIdx.x * 32, by = blockIdx.y * 32;
    const int tx = t & 31, ty = t >> 5;
#pragma unroll
    for (int i = 0; i < 4; i++) {
        int k = by + ty + 8 * i;
        tile[ty + 8 * i][tx] = W[k * DIM + bx + tx];
    }
    __syncthreads();
#pragma unroll
    for (int i = 0; i < 4; i++) {
        int n = bx + ty + 8 * i;
        float v = tile[tx][ty + 8 * i];
        g_Wtf[z * DIM * DIM + n * DIM + by + tx] = __float2half_rn(v);
    }
}

// =====================================================================
// K2: per-edge bias GEMM -> g_EA (x 0.1); direct bucket scatter.
// =====================================================================
__global__ void k_ea(const float* __restrict__ EF, const int* __restrict__ EI,
                     const float* __restrict__ We, const float* __restrict__ be) {
    __shared__ float ef[64][65];
    __shared__ float w[EDIM][NH];
    __shared__ float bsh[NH];
    const int t  = threadIdx.x;
    const int e0 = blockIdx.x * 64;
#pragma unroll
    for (int i = 0; i < 16; i++) {
        int idx = t + 256 * i;
        ef[idx >> 6][idx & 63] = EF[(size_t)e0 * EDIM + idx];
    }
    if (t < EDIM * NH) w[t >> 2][t & 3] = We[t];
    if (t < NH) bsh[t] = be[t];
    __syncthreads();

    const int el = t >> 2, h = t & 3;
    const int e = e0 + el;
    float s = bsh[h];
#pragma unroll
    for (int k = 0; k < EDIM; k++) s += ef[el][k] * w[k][h];
    g_EA[(size_t)e * NH + h] = s * 0.1f;
    if (h == 0) {
        int key = (EI[2 * e] >> 6) * 64 + ((EI[2 * e + 1] >> 6) & 63);
        int pos = atomicAdd(&g_bcnt[key], 1);
        if (pos < BCAP) g_blist[key * BCAP + pos] = e;
    }
}

// =====================================================================
// K1: QKV projection on tensor cores, single fp16 products.
// =====================================================================
#define PJ_BUF(b) ((b) * 24576u)
#define PJ_SMEM   49152

__global__ void __launch_bounds__(256, 2) k_proj_tc(
        const float* __restrict__ bq, const float* __restrict__ bk,
        const float* __restrict__ bv) {
    extern __shared__ char smem[];
    const uint32_t sb = smem_to_u32(smem);
    const int t = threadIdx.x, lane = t & 31, w = t >> 5;
    const int wr = w & 3, wc = w >> 2;
    const int h = blockIdx.x, c0 = h * 64;
    const int n0 = blockIdx.y * 128;
    const int z = blockIdx.z;
    const float* bias = (z == 0) ? bq : (z == 1) ? bk : bv;
    const __half* Wtf = g_Wtf + z * DIM * DIM;

    const int g = lane >> 2, tg = lane & 3;
    const uint32_t cOff = (lane >> 4) * 16;

#pragma unroll
    for (int i = 0; i < 4; i++) {
        int e = t + 256 * i;
        int row = e >> 3, c8 = e & 7;
        uint32_t sw = SW128((uint32_t)(row * 128 + c8 * 16));
        CP_ASYNC16(sb + PJ_BUF(0) + sw, g_Xf + (size_t)(n0 + row) * DIM + c8 * 8);
    }
#pragma unroll
    for (int i = 0; i < 2; i++) {
        int e = t + 256 * i;
        int row = e >> 3, c8 = e & 7;
        uint32_t sw = SW128((uint32_t)(row * 128 + c8 * 16));
        CP_ASYNC16(sb + PJ_BUF(0) + 16384 + sw, Wtf + (size_t)(c0 + row) * DIM + c8 * 8);
    }
    CP_COMMIT();
    CP_WAIT0();
    __syncthreads();

    float acc[2][4][4];
#pragma unroll
    for (int f = 0; f < 2; f++)
#pragma unroll
        for (int fm = 0; fm < 4; fm++)
#pragma unroll
            for (int k = 0; k < 4; k++) acc[f][fm][k] = 0.f;

    for (int ch = 0; ch < 4; ch++) {
        const int b = ch & 1;
        if (ch < 3) {
            const int kc = (ch + 1) * 64;
#pragma unroll
            for (int i = 0; i < 4; i++) {
                int e = t + 256 * i;
                int row = e >> 3, c8 = e & 7;
                uint32_t sw = SW128((uint32_t)(row * 128 + c8 * 16));
                CP_ASYNC16(sb + PJ_BUF(b ^ 1) + sw,
                           g_Xf + (size_t)(n0 + row) * DIM + kc + c8 * 8);
            }
#pragma unroll
            for (int i = 0; i < 2; i++) {
                int e = t + 256 * i;
                int row = e >> 3, c8 = e & 7;
                uint32_t sw = SW128((uint32_t)(row * 128 + c8 * 16));
                CP_ASYNC16(sb + PJ_BUF(b ^ 1) + 16384 + sw,
                           Wtf + (size_t)(c0 + row) * DIM + kc + c8 * 8);
            }
            CP_COMMIT();
        }
        const uint32_t sA = sb + PJ_BUF(b), sB = sA + 16384;
#pragma unroll
        for (int ks = 0; ks < 4; ks++) {
            uint32_t aH[2][4], bH[2][4];
#pragma unroll
            for (int f = 0; f < 2; f++) {
                uint32_t byte = (wr * 32 + f * 16 + (lane & 15)) * 128 + ks * 32 + cOff;
                ldsm4(aH[f], sA + SW128(byte));
            }
#pragma unroll
            for (int fg = 0; fg < 2; fg++) {
                uint32_t byte = (wc * 32 + fg * 16 + (lane & 15)) * 128 + ks * 32 + cOff;
                ldsm4(bH[fg], sB + SW128(byte));
            }
#pragma unroll
            for (int f = 0; f < 2; f++)
#pragma unroll
                for (int fg = 0; fg < 2; fg++) {
                    mma_f16(acc[f][2*fg],   aH[f], bH[fg][0], bH[fg][2]);
                    mma_f16(acc[f][2*fg+1], aH[f], bH[fg][1], bH[fg][3]);
                }
        }
        if (ch < 3) CP_WAIT0();
        __syncthreads();
    }

    // epilogue
#pragma unroll
    for (int f = 0; f < 2; f++) {
        int row0 = n0 + wr * 32 + f * 16 + g;
#pragma unroll
        for (int fm = 0; fm < 4; fm++) {
            int cl = wc * 32 + fm * 8 + tg * 2;
            float b0 = bias[c0 + cl], b1 = bias[c0 + cl + 1];
            float v0 = acc[f][fm][0] + b0, v1 = acc[f][fm][1] + b1;
            float v2 = acc[f][fm][2] + b0, v3 = acc[f][fm][3] + b1;
            if (z == 0) { v0 *= QSC; v1 *= QSC; v2 *= QSC; v3 *= QSC; }
            if (z < 2) {
                __half* dst = (z == 0) ? g_Qh : g_Kh;
                size_t i0 = ((size_t)h * NN + row0) * HD + cl;
                size_t i8 = ((size_t)h * NN + row0 + 8) * HD + cl;
                *(uint32_t*)&dst[i0] = cvtf16(v0, v1);
                *(uint32_t*)&dst[i8] = cvtf16(v2, v3);
            } else {
                float vv[4] = {v0, v1, v2, v3};
#pragma unroll
                for (int q = 0; q < 4; q++) {
                    int d = cl + (q & 1);
                    int m = row0 + (q >> 1) * 8;
                    g_Vh[((size_t)h * HD + d) * NN + m] = __float2half_rn(vv[q]);
                }
            }
        }
    }
}

// =====================================================================
// K3: FUSED attention v8b (R15). QK fp16 single, PV fp16 single.
// grid = (nb, h) so same-head CTAs are schedule-adjacent (L2 locality).
// smem: ADJ(b) @b*17408 | KV(b) @34816+b*16384 | sums @67584 ; 68096 B
// =====================================================================
#define FB_ADJ(b) ((b) * 17408u)
#define FB_KV(b)  (34816u + (b) * 16384u)
#define FB_SUM    67584u
#define FS_SMEM   68096

__global__ void __launch_bounds__(256, 2) k_fused(const float* __restrict__ adj,
                                                  const int* __restrict__ EI) {
    extern __shared__ char smem[];
    const uint32_t sb = smem_to_u32(smem);
    const int t = threadIdx.x, lane = t & 31, w = t >> 5;
    const int wr = w & 3, wc = w >> 2;
    const int h = blockIdx.y, nb = blockIdx.x, n0 = nb * 64;

    const int g  = lane >> 2, tg = lane & 3;
    const int rl = wr * 16 + g;
    const uint32_t aRow = wr * 16 + (lane & 15);
    const uint32_t cOff = (lane >> 4) * 16;

    const __half* Khb = g_Kh + (size_t)h * NN * HD;
    const __half* Vhb = g_Vh + (size_t)h * HD * NN;

    // ---------- prologue ----------
    const int kvc = t & 7;
#pragma unroll
    for (int i = 0; i < 2; i++) {
        int r = (t >> 3) + 32 * i;
        uint32_t sw = SW128((uint32_t)(r * 128 + kvc * 16));
        CP_ASYNC16(sb + FB_KV(0) + sw,         Khb + (size_t)r * HD + kvc * 8);
        CP_ASYNC16(sb + FB_KV(0) + 8192 + sw,  Vhb + (size_t)r * NN + kvc * 8);
    }
    CP_COMMIT();
    {
        const uint4* qh = (const uint4*)(g_Qh + ((size_t)h * NN + n0) * HD);
#pragma unroll
        for (int i = 0; i < 2; i++) {
            int e = t + 256 * i;
            uint32_t sw = SW128((uint32_t)e * 16);
            *(uint4*)(smem + FB_ADJ(0) + sw) = qh[e];
        }
    }
    __syncthreads();

    uint32_t aQH[4][4];
#pragma unroll
    for (int ks = 0; ks < 4; ks++) {
        uint32_t byte = aRow * 128 + ks * 32 + cOff;
        ldsm4(aQH[ks], sb + FB_ADJ(0) + SW128(byte));
    }
    __syncthreads();

#pragma unroll
    for (int i = 0; i < 4; i++) {
        int idx = t + 256 * i;
        int row = idx >> 4, c4 = idx & 15;
        CP_ASYNC16(sb + FB_ADJ(0) + (uint32_t)(row * 272 + c4 * 16),
                   adj + (size_t)(n0 + row) * NN + c4 * 4);
    }
    CP_COMMIT();
    CP_WAIT0();
    __syncthreads();

    float oacc[8][4];
#pragma unroll
    for (int fd = 0; fd < 8; fd++)
#pragma unroll
        for (int k = 0; k < 4; k++) oacc[fd][k] = 0.f;
    float rs0a = 0.f, rs0b = 0.f, rs8a = 0.f, rs8b = 0.f;

    for (int j = 0; j < 64; j++) {
        const int b = j & 1;
        const uint32_t sKH = sb + FB_KV(b);
        const uint32_t sVH = sKH + 8192;
        float* At = (float*)(smem + FB_ADJ(b));

        {
            int key = nb * 64 + j;
            int cnt = g_bcnt[key];
            const int* bl = g_blist + key * BCAP;
            for (int i = t; i < cnt; i += 256) {
                int e = bl[i];
                atomicAdd(&At[(EI[2 * e] & 63) * 68 + (EI[2 * e + 1] & 63)],
                          g_EA[(size_t)e * NH + h]);
            }
        }
        float qk[4][4];
#pragma unroll
        for (int fi = 0; fi < 4; fi++)
#pragma unroll
            for (int k = 0; k < 4; k++) qk[fi][k] = CB;
#pragma unroll
        for (int ks = 0; ks < 4; ks++) {
            uint32_t bH[2][4];
#pragma unroll
            for (int fg = 0; fg < 2; fg++) {
                uint32_t bb = (wc * 32 + fg * 16 + (lane & 15)) * 128 + ks * 32 + cOff;
                ldsm4(bH[fg], sKH + SW128(bb));
            }
#pragma unroll
            for (int fg = 0; fg < 2; fg++) {
                mma_f16(qk[2*fg],   aQH[ks], bH[fg][0], bH[fg][2]);
                mma_f16(qk[2*fg+1], aQH[ks], bH[fg][1], bH[fg][3]);
            }
        }
        if (j < 63) {
            const int m1 = (j + 1) * 64;
#pragma unroll
            for (int i = 0; i < 2; i++) {
                int r = (t >> 3) + 32 * i;
                uint32_t sw = SW128((uint32_t)(r * 128 + kvc * 16));
                CP_ASYNC16(sb + FB_KV(b ^ 1) + sw,        Khb + (size_t)(m1 + r) * HD + kvc * 8);
                CP_ASYNC16(sb + FB_KV(b ^ 1) + 8192 + sw, Vhb + (size_t)r * NN + m1 + kvc * 8);
            }
#pragma unroll
            for (int i = 0; i < 4; i++) {
                int idx = t + 256 * i;
                int row = idx >> 4, c4 = idx & 15;
                CP_ASYNC16(sb + FB_ADJ(b ^ 1) + (uint32_t)(row * 272 + c4 * 16),
                           adj + (size_t)(n0 + row) * NN + m1 + c4 * 4);
            }
            CP_COMMIT();
        }
        __syncthreads();   // SYNC1

        uint32_t pH0[4], pH8[4];
        const float* At0 = At + rl * 68 + wc * 32 + tg * 2;
        const float* At8 = At0 + 8 * 68;
#pragma unroll
        for (int fi = 0; fi < 4; fi++) {
            float2 a0 = *(const float2*)(At0 + fi * 8);
            float2 a8 = *(const float2*)(At8 + fi * 8);
            float p0 = ex2(fmaf(C10, a0.x, qk[fi][0]));
            float p1 = ex2(fmaf(C10, a0.y, qk[fi][1]));
            float p2 = ex2(fmaf(C10, a8.x, qk[fi][2]));
            float p3 = ex2(fmaf(C10, a8.y, qk[fi][3]));
            if (fi & 1) { rs0b += p0 + p1; rs8b += p2 + p3; }
            else        { rs0a += p0 + p1; rs8a += p2 + p3; }
            pH0[fi] = cvtf16(p0, p1);
            pH8[fi] = cvtf16(p2, p3);
        }
#pragma unroll
        for (int ks2 = 0; ks2 < 2; ks2++) {
            uint32_t aH[4] = {pH0[2*ks2], pH8[2*ks2], pH0[2*ks2+1], pH8[2*ks2+1]};
#pragma unroll
            for (int fg = 0; fg < 4; fg++) {
                uint32_t bb = (fg * 16 + (lane & 15)) * 128 + wc * 64 + ks2 * 32 + cOff;
                uint32_t bH[4];
                ldsm4(bH, sVH + SW128(bb));
                mma_f16(oacc[2*fg],   aH, bH[0], bH[2]);
                mma_f16(oacc[2*fg+1], aH, bH[1], bH[3]);
            }
        }
        CP_WAIT0();
        __syncthreads();   // SYNC2
    }

    // ---- epilogue: write O as single fp16 ----
    float rowsum0 = rs0a + rs0b, rowsum8 = rs8a + rs8b;
    rowsum0 += __shfl_xor_sync(0xffffffffu, rowsum0, 1);
    rowsum0 += __shfl_xor_sync(0xffffffffu, rowsum0, 2);
    rowsum8 += __shfl_xor_sync(0xffffffffu, rowsum8, 1);
    rowsum8 += __shfl_xor_sync(0xffffffffu, rowsum8, 2);
    float* sums = (float*)(smem + FB_SUM);
    if (tg == 0) {
        sums[wc * 64 + rl] = rowsum0;
        sums[wc * 64 + rl + 8] = rowsum8;
    }
    float* buf = (float*)(smem + FB_ADJ(0));
    __syncthreads();
    if (wc == 1) {
#pragma unroll
        for (int fd = 0; fd < 8; fd++) {
            int col = (fd >> 1) * 16 + (fd & 1) * 8 + tg * 2;
            buf[rl * 68 + col]           = oacc[fd][0];
            buf[rl * 68 + col + 1]       = oacc[fd][1];
            buf[(rl + 8) * 68 + col]     = oacc[fd][2];
            buf[(rl + 8) * 68 + col + 1] = oacc[fd][3];
        }
    }
    __syncthreads();
    if (wc == 0) {
        const float ri0 = 1.f / (sums[rl] + sums[64 + rl]);
        const float ri8 = 1.f / (sums[rl + 8] + sums[64 + rl + 8]);
#pragma unroll
        for (int fd = 0; fd < 8; fd++) {
            int col = (fd >> 1) * 16 + (fd & 1) * 8 + tg * 2;
            float v0 = (oacc[fd][0] + buf[rl * 68 + col]) * ri0;
            float v1 = (oacc[fd][1] + buf[rl * 68 + col + 1]) * ri0;
            float v2 = (oacc[fd][2] + buf[(rl + 8) * 68 + col]) * ri8;
            float v3 = (oacc[fd][3] + buf[(rl + 8) * 68 + col + 1]) * ri8;
            size_t i0 = (size_t)(n0 + rl) * DIM + h * HD + col;
            size_t i8 = (size_t)(n0 + rl + 8) * DIM + h * HD + col;
            *(uint32_t*)&g_Of[i0] = cvtf16(v0, v1);
            *(uint32_t*)&g_Of[i8] = cvtf16(v2, v3);
        }
    }
}

// =====================================================================
// K4: output projection (fp16 single) + residual + LayerNorm.
// =====================================================================
#define OP_BUF(b) ((b) * 36864u)
#define OP_SUM    73728u
#define OP_SMEM   74880

__global__ void __launch_bounds__(256, 2) k_oproj_ln(
        const float* __restrict__ bo, const float* __restrict__ X,
        const float* __restrict__ gamma, const float* __restrict__ beta,
        float* __restrict__ out) {
    extern __shared__ char smem[];
    const uint32_t sb = smem_to_u32(smem);
    const int t = threadIdx.x, lane = t & 31, w = t >> 5;
    const int r0 = blockIdx.x * 32;
    const int g = lane >> 2, tg = lane & 3;
    const uint32_t cOff = (lane >> 4) * 16;
    const __half* Wtf = g_Wtf + 3 * DIM * DIM;

    {
        int row = t >> 3, c8 = t & 7;
        uint32_t sw = SW128((uint32_t)(row * 128 + c8 * 16));
        CP_ASYNC16(sb + OP_BUF(0) + sw, g_Of + (size_t)(r0 + row) * DIM + c8 * 8);
#pragma unroll
        for (int i = 0; i < 8; i++) {
            int rb = (t >> 3) + 32 * i;
            uint32_t swb = SW128((uint32_t)(rb * 128 + c8 * 16));
            CP_ASYNC16(sb + OP_BUF(0) + 4096 + swb, Wtf + (size_t)rb * DIM + c8 * 8);
        }
    }
    CP_COMMIT();
    CP_WAIT0();
    __syncthreads();

    float acc[2][4][4];
#pragma unroll
    for (int f = 0; f < 2; f++)
#pragma unroll
        for (int fm = 0; fm < 4; fm++)
#pragma unroll
            for (int k = 0; k < 4; k++) acc[f][fm][k] = 0.f;

    for (int ch = 0; ch < 4; ch++) {
        const int b = ch & 1;
        if (ch < 3) {
            const int kc = (ch + 1) * 64;
            int row = t >> 3, c8 = t & 7;
            uint32_t sw = SW128((uint32_t)(row * 128 + c8 * 16));
            CP_ASYNC16(sb + OP_BUF(b ^ 1) + sw,
                       g_Of + (size_t)(r0 + row) * DIM + kc + c8 * 8);
#pragma unroll
            for (int i = 0; i < 8; i++) {
                int rb = (t >> 3) + 32 * i;
                uint32_t swb = SW128((uint32_t)(rb * 128 + c8 * 16));
                CP_ASYNC16(sb + OP_BUF(b ^ 1) + 4096 + swb,
                           Wtf + (size_t)rb * DIM + kc + c8 * 8);
            }
            CP_COMMIT();
        }
        const uint32_t sA = sb + OP_BUF(b), sB = sA + 4096;
#pragma unroll
        for (int ks = 0; ks < 4; ks++) {
            uint32_t aH[2][4], bH[2][4];
#pragma unroll
            for (int f = 0; f < 2; f++) {
                uint32_t byte = (f * 16 + (lane & 15)) * 128 + ks * 32 + cOff;
                ldsm4(aH[f], sA + SW128(byte));
            }
#pragma unroll
            for (int fg = 0; fg < 2; fg++) {
                uint32_t byte = (w * 32 + fg * 16 + (lane & 15)) * 128 + ks * 32 + cOff;
                ldsm4(bH[fg], sB + SW128(byte));
            }
#pragma unroll
            for (int f = 0; f < 2; f++)
#pragma unroll
                for (int fg = 0; fg < 2; fg++) {
                    mma_f16(acc[f][2*fg],   aH[f], bH[fg][0], bH[fg][2]);
                    mma_f16(acc[f][2*fg+1], aH[f], bH[fg][1], bH[fg][3]);
                }
        }
        if (ch < 3) CP_WAIT0();
        __syncthreads();
    }

    // bias + residual
#pragma unroll
    for (int f = 0; f < 2; f++) {
#pragma unroll
        for (int fm = 0; fm < 4; fm++) {
            int col = w * 32 + fm * 8 + tg * 2;
            float2 bb = *(const float2*)&bo[col];
            float2 x0 = *(const float2*)&X[(size_t)(r0 + f * 16 + g) * DIM + col];
            float2 x8 = *(const float2*)&X[(size_t)(r0 + f * 16 + g + 8) * DIM + col];
            acc[f][fm][0] += bb.x + x0.x;
            acc[f][fm][1] += bb.y + x0.y;
            acc[f][fm][2] += bb.x + x8.x;
            acc[f][fm][3] += bb.y + x8.y;
        }
    }

    // LayerNorm: cross-warp reduce via smem [32][9]
    float* sums = (float*)(smem + OP_SUM);
#pragma unroll
    for (int f = 0; f < 2; f++) {
        float s0 = 0.f, s8 = 0.f;
#pragma unroll
        for (int fm = 0; fm < 4; fm++) {
            s0 += acc[f][fm][0] + acc[f][fm][1];
            s8 += acc[f][fm][2] + acc[f][fm][3];
        }
        s0 += __shfl_xor_sync(0xffffffffu, s0, 1);
        s0 += __shfl_xor_sync(0xffffffffu, s0, 2);
        s8 += __shfl_xor_sync(0xffffffffu, s8, 1);
        s8 += __shfl_xor_sync(0xffffffffu, s8, 2);
        if (tg == 0) {
            sums[(f * 16 + g) * 9 + w] = s0;
            sums[(f * 16 + g + 8) * 9 + w] = s8;
        }
    }
    __syncthreads();
    float mu[2][2];
#pragma unroll
    for (int f = 0; f < 2; f++) {
        float m0 = 0.f, m8 = 0.f;
#pragma unroll
        for (int ww = 0; ww < 8; ww++) {
            m0 += sums[(f * 16 + g) * 9 + ww];
            m8 += sums[(f * 16 + g + 8) * 9 + ww];
        }
        mu[f][0] = m0 * (1.f / DIM);
        mu[f][1] = m8 * (1.f / DIM);
    }
    __syncthreads();
#pragma unroll
    for (int f = 0; f < 2; f++) {
        float q0 = 0.f, q8 = 0.f;
#pragma unroll
        for (int fm = 0; fm < 4; fm++) {
            acc[f][fm][0] -= mu[f][0]; acc[f][fm][1] -= mu[f][0];
            acc[f][fm][2] -= mu[f][1]; acc[f][fm][3] -= mu[f][1];
            q0 += acc[f][fm][0] * acc[f][fm][0] + acc[f][fm][1] * acc[f][fm][1];
            q8 += acc[f][fm][2] * acc[f][fm][2] + acc[f][fm][3] * acc[f][fm][3];
        }
        q0 += __shfl_xor_sync(0xffffffffu, q0, 1);
        q0 += __shfl_xor_sync(0xffffffffu, q0, 2);
        q8 += __shfl_xor_sync(0xffffffffu, q8, 1);
        q8 += __shfl_xor_sync(0xffffffffu, q8, 2);
        if (tg == 0) {
            sums[(f * 16 + g) * 9 + w] = q0;
            sums[(f * 16 + g + 8) * 9 + w] = q8;
        }
    }
    __syncthreads();
#pragma unroll
    for (int f = 0; f < 2; f++) {
        float v0 = 0.f, v8 = 0.f;
#pragma unroll
        for (int ww = 0; ww < 8; ww++) {
            v0 += sums[(f * 16 + g) * 9 + ww];
            v8 += sums[(f * 16 + g + 8) * 9 + ww];
        }
        float rs0 = rsqrtf(v0 * (1.f / DIM) + LN_EPS);
        float rs8 = rsqrtf(v8 * (1.f / DIM) + LN_EPS);
#pragma unroll
        for (int fm = 0; fm < 4; fm++) {
            int col = w * 32 + fm * 8 + tg * 2;
            float2 gm = *(const float2*)&gamma[col];
            float2 bt = *(const float2*)&beta[col];
            float2 o0 = { gm.x * acc[f][fm][0] * rs0 + bt.x,
                          gm.y * acc[f][fm][1] * rs0 + bt.y };
            float2 o8 = { gm.x * acc[f][fm][2] * rs8 + bt.x,
                          gm.y * acc[f][fm][3] * rs8 + bt.y };
            *(float2*)&out[(size_t)(r0 + f * 16 + g) * DIM + col] = o0;
            *(float2*)&out[(size_t)(r0 + f * 16 + g + 8) * DIM + col] = o8;
        }
    }
}

// =====================================================================
extern "C" void kernel_launch(void* const* d_in, const int* in_sizes, int n_in,
                              void* d_out, int out_size) {
    const float* X    = (const float*)d_in[0];
    const float* adj  = (const float*)d_in[1];
    const float* EF   = (const float*)d_in[2];
    const int*   EI   = (const int*)  d_in[3];
    const float* Wq   = (const float*)d_in[4];
    const float* bq   = (const float*)d_in[5];
    const float* Wk   = (const float*)d_in[6];
    const float* bk   = (const float*)d_in[7];
    const float* Wv   = (const float*)d_in[8];
    const float* bv   = (const float*)d_in[9];
    const float* We   = (const float*)d_in[10];
    const float* be   = (const float*)d_in[11];
    const float* Wo   = (const float*)d_in[12];
    const float* bo   = (const float*)d_in[13];
    const float* gam  = (const float*)d_in[14];
    const float* bet  = (const float*)d_in[15];
    float* out = (float*)d_out;

    cudaFuncSetAttribute(k_proj_tc,  cudaFuncAttributeMaxDynamicSharedMemorySize, PJ_SMEM);
    cudaFuncSetAttribute(k_fused,    cudaFuncAttributeMaxDynamicSharedMemorySize, FS_SMEM);
    cudaFuncSetAttribute(k_oproj_ln, cudaFuncAttributeMaxDynamicSharedMemorySize, OP_SMEM);

    k_split   <<<dim3(8, 8, 5), 256>>>(X, Wq, Wk, Wv, Wo);
    k_ea      <<<NE / 64, 256>>>(EF, EI, We, be);
    k_proj_tc <<<dim3(4, 32, 3), 256, PJ_SMEM>>>(bq, bk, bv);
    k_fused   <<<dim3(64, NH), 256, FS_SMEM>>>(adj, EI);
    k_oproj_ln<<<NN / 32, 256, OP_SMEM>>>(bo, X, gam, bet, out);
}